// round 9
// baseline (speedup 1.0000x reference)
#include <cuda_runtime.h>
#include <cstdint>

#define Hh 56
#define Ww 56
#define HO 58
#define WO 58
#define PLANE_IN  3136   // 56*56
#define PLANE_OUT 3364   // 58*58
// C fixed at 128 by the generator
#define C_LOG2 7
#define C_MASK 127

__global__ void __launch_bounds__(256, 8)
weight_pad2d_kernel(const float* __restrict__ x,
                    const float* __restrict__ topW,
                    const float* __restrict__ botW,
                    const float* __restrict__ leftW,
                    const float* __restrict__ rightW,
                    const float* __restrict__ topleftW,
                    const float* __restrict__ toprightW,
                    const float* __restrict__ botleftW,
                    const float* __restrict__ botrightW,
                    const int* __restrict__ num_patches_ptr,
                    int planes,
                    float* __restrict__ out)
{
    const int tid  = threadIdx.x;
    const int warp = tid >> 5;           // 0..7
    const int lane = tid & 31;

    const int P  = *num_patches_ptr;
    const int PP = P * P;

    const bool ld = (lane < 28);   // lanes 0..27 load (56 floats)
    const bool st = (lane < 29);   // lanes 0..28 store (58 floats)

    for (int plane = blockIdx.x; plane < planes; plane += gridDim.x) {
        const int bidx = plane >> C_LOG2;
        const int ch   = plane & C_MASK;

        const float* __restrict__ xp = x   + (size_t)plane * PLANE_IN;
        float*       __restrict__ op = out + (size_t)plane * PLANE_OUT;

        // ---- phase 1 FIRST: batch all 7 interior-source loads (MLP = 7) ----
        // warp w owns input rows ir = w, w+8, ..., w+48
        float2 g[7];
        #pragma unroll
        for (int k = 0; k < 7; k++) {
            g[k] = make_float2(0.0f, 0.0f);
            if (ld) g[k] = __ldcs((const float2*)(xp + (warp + 8 * k) * Ww + 2 * lane));
        }

        // masks / weights (ALU overlaps with load latency)
        const unsigned q1 = (unsigned)bidx / (unsigned)P;
        const int colp    = bidx - (int)(q1 * (unsigned)P);       // bidx % P
        const unsigned q2 = (unsigned)bidx / (unsigned)PP;
        const int within  = bidx - (int)(q2 * (unsigned)PP);      // bidx % PP

        const bool topz   = within < P;
        const bool botz   = within >= PP - P;
        const bool leftz  = colp == 0;
        const bool rightz = colp == (P - 1);

        const float wLr = leftz  ? 0.0f : leftW[ch];
        const float wRr = rightz ? 0.0f : rightW[ch];

        // ---- phase 2: interior rows r = 1..56 (shuffle + select + store) ----
        #pragma unroll
        for (int k = 0; k < 7; k++) {
            const int r = 1 + warp + 8 * k;
            const float upx = __shfl_up_sync(0xffffffffu, g[k].x, 1);
            const float upy = __shfl_up_sync(0xffffffffu, g[k].y, 1);
            if (st) {
                const float o_lo = (lane == 0)  ? wLr * (g[k].x + g[k].y) : upy;
                const float o_hi = (lane == 28) ? wRr * (upx + upy)       : g[k].x;
                __stcs((float2*)(op + r * WO + 2 * lane), make_float2(o_lo, o_hi));
            }
        }

        // ---- edge rows LAST: reloads of rows 0,1,54,55 hit L1 (just fetched
        //      by warps 0/1/6/7 of this block). Default caching on purpose. ----
        if (tid < 64) {
            // top row r=0
            const int c = tid;
            if (c < WO) {
                float v;
                if (c == 0) {
                    v = (topz || leftz) ? 0.0f : topleftW[ch] * xp[0];
                } else if (c == WO - 1) {
                    v = (topz || rightz) ? 0.0f : toprightW[ch] * xp[Ww - 1];
                } else {
                    v = topz ? 0.0f : topW[ch] * (xp[c - 1] + xp[Ww + c - 1]);
                }
                __stcs(op + c, v);
            }
        } else if (tid < 128) {
            // bottom row r=57
            const int c = tid - 64;
            if (c < WO) {
                const float* x54 = xp + (Hh - 2) * Ww;
                const float* x55 = xp + (Hh - 1) * Ww;
                float v;
                if (c == 0) {
                    v = (botz || leftz) ? 0.0f : botleftW[ch] * x55[0];
                } else if (c == WO - 1) {
                    v = (botz || rightz) ? 0.0f : botrightW[ch] * x55[Ww - 1];
                } else {
                    v = botz ? 0.0f : botW[ch] * (x54[c - 1] + x55[c - 1]);
                }
                __stcs(op + (HO - 1) * WO + c, v);
            }
        }
    }
}

extern "C" void kernel_launch(void* const* d_in, const int* in_sizes, int n_in,
                              void* d_out, int out_size)
{
    const float* x         = (const float*)d_in[0];
    const float* topW      = (const float*)d_in[1];
    const float* botW      = (const float*)d_in[2];
    const float* leftW     = (const float*)d_in[3];
    const float* rightW    = (const float*)d_in[4];
    const float* topleftW  = (const float*)d_in[5];
    const float* toprightW = (const float*)d_in[6];
    const float* botleftW  = (const float*)d_in[7];
    const float* botrightW = (const float*)d_in[8];
    const int*   num_patches = (const int*)d_in[10];

    const int planes = in_sizes[0] / PLANE_IN;   // b * C = 16384

    int grid = 148 * 8;
    if (grid > planes) grid = planes;

    weight_pad2d_kernel<<<grid, 256>>>(
        x, topW, botW, leftW, rightW,
        topleftW, toprightW, botleftW, botrightW,
        num_patches, planes, (float*)d_out);
}

// round 10
// speedup vs baseline: 1.0906x; 1.0906x over previous
#include <cuda_runtime.h>
#include <cstdint>

#define Hh 56
#define Ww 56
#define HO 58
#define WO 58
#define PLANE_IN  3136   // 56*56
#define PLANE_OUT 3364   // 58*58
// C fixed at 128 by the generator
#define C_LOG2 7
#define C_MASK 127

__global__ void __launch_bounds__(256, 8)
weight_pad2d_kernel(const float* __restrict__ x,
                    const float* __restrict__ topW,
                    const float* __restrict__ botW,
                    const float* __restrict__ leftW,
                    const float* __restrict__ rightW,
                    const float* __restrict__ topleftW,
                    const float* __restrict__ toprightW,
                    const float* __restrict__ botleftW,
                    const float* __restrict__ botrightW,
                    const int* __restrict__ num_patches_ptr,
                    int planes,
                    float* __restrict__ out)
{
    const int tid  = threadIdx.x;
    const int warp = tid >> 5;           // 0..7
    const int lane = tid & 31;

    const int P  = *num_patches_ptr;
    const int PP = P * P;

    const bool ld = (lane < 28);   // lanes 0..27 load (56 floats)
    const bool st = (lane < 29);   // lanes 0..28 store (58 floats)

    for (int plane = blockIdx.x; plane < planes; plane += gridDim.x) {
        const int bidx = plane >> C_LOG2;
        const int ch   = plane & C_MASK;

        const float* __restrict__ xp = x   + (size_t)plane * PLANE_IN;
        float*       __restrict__ op = out + (size_t)plane * PLANE_OUT;

        // ---- phase 1: batch all 7 interior-source loads (MLP = 7) ----
        // warp w owns input rows ir = w, w+8, ..., w+48.
        // Row-groups k=0 (rows 0..7) and k=6 (rows 48..55) keep default caching:
        // rows 0,1,54,55 are re-read by the edge warps below and must hit L1.
        float2 g[7];
        #pragma unroll
        for (int k = 0; k < 7; k++) {
            g[k] = make_float2(0.0f, 0.0f);
            if (ld) {
                const float2* p = (const float2*)(xp + (warp + 8 * k) * Ww + 2 * lane);
                g[k] = (k == 0 || k == 6) ? *p : __ldcs(p);
            }
        }

        // ---- masks / weights: integer math overlaps the load drain ----
        const unsigned q1 = (unsigned)bidx / (unsigned)P;
        const int colp    = bidx - (int)(q1 * (unsigned)P);       // bidx % P
        const unsigned q2 = (unsigned)bidx / (unsigned)PP;
        const int within  = bidx - (int)(q2 * (unsigned)PP);      // bidx % PP

        const bool topz   = within < P;
        const bool botz   = within >= PP - P;
        const bool leftz  = colp == 0;
        const bool rightz = colp == (P - 1);

        const float wLr = leftz  ? 0.0f : leftW[ch];
        const float wRr = rightz ? 0.0f : rightW[ch];

        // ---- edge rows: issued while the g[] loads are still in flight ----
        if (tid < 64) {
            // top row r=0
            const int c = tid;
            if (c < WO) {
                float v;
                if (c == 0) {
                    v = (topz || leftz) ? 0.0f : topleftW[ch] * xp[0];
                } else if (c == WO - 1) {
                    v = (topz || rightz) ? 0.0f : toprightW[ch] * xp[Ww - 1];
                } else {
                    v = topz ? 0.0f : topW[ch] * (xp[c - 1] + xp[Ww + c - 1]);
                }
                __stcs(op + c, v);
            }
        } else if (tid < 128) {
            // bottom row r=57
            const int c = tid - 64;
            if (c < WO) {
                const float* x54 = xp + (Hh - 2) * Ww;
                const float* x55 = xp + (Hh - 1) * Ww;
                float v;
                if (c == 0) {
                    v = (botz || leftz) ? 0.0f : botleftW[ch] * x55[0];
                } else if (c == WO - 1) {
                    v = (botz || rightz) ? 0.0f : botrightW[ch] * x55[Ww - 1];
                } else {
                    v = botz ? 0.0f : botW[ch] * (x54[c - 1] + x55[c - 1]);
                }
                __stcs(op + (HO - 1) * WO + c, v);
            }
        }

        // ---- phase 2: interior rows r = 1..56 (shuffle + select + store) ----
        #pragma unroll
        for (int k = 0; k < 7; k++) {
            const int r = 1 + warp + 8 * k;
            const float upx = __shfl_up_sync(0xffffffffu, g[k].x, 1);
            const float upy = __shfl_up_sync(0xffffffffu, g[k].y, 1);
            if (st) {
                const float o_lo = (lane == 0)  ? wLr * (g[k].x + g[k].y) : upy;
                const float o_hi = (lane == 28) ? wRr * (upx + upy)       : g[k].x;
                __stcs((float2*)(op + r * WO + 2 * lane), make_float2(o_lo, o_hi));
            }
        }
    }
}

extern "C" void kernel_launch(void* const* d_in, const int* in_sizes, int n_in,
                              void* d_out, int out_size)
{
    const float* x         = (const float*)d_in[0];
    const float* topW      = (const float*)d_in[1];
    const float* botW      = (const float*)d_in[2];
    const float* leftW     = (const float*)d_in[3];
    const float* rightW    = (const float*)d_in[4];
    const float* topleftW  = (const float*)d_in[5];
    const float* toprightW = (const float*)d_in[6];
    const float* botleftW  = (const float*)d_in[7];
    const float* botrightW = (const float*)d_in[8];
    const int*   num_patches = (const int*)d_in[10];

    const int planes = in_sizes[0] / PLANE_IN;   // b * C = 16384

    int grid = 148 * 8;
    if (grid > planes) grid = planes;

    weight_pad2d_kernel<<<grid, 256>>>(
        x, topW, botW, leftW, rightW,
        topleftW, toprightW, botleftW, botrightW,
        num_patches, planes, (float*)d_out);
}

// round 11
// speedup vs baseline: 1.1041x; 1.0124x over previous
#include <cuda_runtime.h>
#include <cstdint>

#define Hh 56
#define Ww 56
#define HO 58
#define WO 58
#define PLANE_IN  3136   // 56*56
#define PLANE_OUT 3364   // 58*58
// C fixed at 128 by the generator
#define C_LOG2 7
#define C_MASK 127

__global__ void __launch_bounds__(256, 8)
weight_pad2d_kernel(const float* __restrict__ x,
                    const float* __restrict__ topW,
                    const float* __restrict__ botW,
                    const float* __restrict__ leftW,
                    const float* __restrict__ rightW,
                    const float* __restrict__ topleftW,
                    const float* __restrict__ toprightW,
                    const float* __restrict__ botleftW,
                    const float* __restrict__ botrightW,
                    const int* __restrict__ num_patches_ptr,
                    int planes,
                    float* __restrict__ out)
{
    const int tid  = threadIdx.x;
    const int warp = tid >> 5;           // 0..7
    const int lane = tid & 31;

    const int P  = *num_patches_ptr;
    const int PP = P * P;

    const bool ld = (lane < 28);   // lanes 0..27 load (56 floats)
    const bool st = (lane < 29);   // lanes 0..28 store (58 floats)

    for (int plane = blockIdx.x; plane < planes; plane += gridDim.x) {
        const int bidx = plane >> C_LOG2;
        const int ch   = plane & C_MASK;

        const unsigned q1 = (unsigned)bidx / (unsigned)P;
        const int colp    = bidx - (int)(q1 * (unsigned)P);       // bidx % P
        const unsigned q2 = (unsigned)bidx / (unsigned)PP;
        const int within  = bidx - (int)(q2 * (unsigned)PP);      // bidx % PP

        const bool topz   = within < P;
        const bool botz   = within >= PP - P;
        const bool leftz  = colp == 0;
        const bool rightz = colp == (P - 1);

        const float* __restrict__ xp = x   + (size_t)plane * PLANE_IN;
        float*       __restrict__ op = out + (size_t)plane * PLANE_OUT;

        // ---- peeled top row (r=0): warps 0,1 scalar, default caching ----
        if (tid < 64) {
            const int c = tid;
            if (c < WO) {
                float v;
                if (c == 0) {
                    v = (topz || leftz) ? 0.0f : topleftW[ch] * xp[0];
                } else if (c == WO - 1) {
                    v = (topz || rightz) ? 0.0f : toprightW[ch] * xp[Ww - 1];
                } else {
                    v = topz ? 0.0f : topW[ch] * (xp[c - 1] + xp[Ww + c - 1]);
                }
                op[c] = v;
            }
        } else if (tid < 128) {
            // ---- peeled bottom row (r=57): warps 2,3 scalar ----
            const int c = tid - 64;
            if (c < WO) {
                const float* x54 = xp + (Hh - 2) * Ww;
                const float* x55 = xp + (Hh - 1) * Ww;
                float v;
                if (c == 0) {
                    v = (botz || leftz) ? 0.0f : botleftW[ch] * x55[0];
                } else if (c == WO - 1) {
                    v = (botz || rightz) ? 0.0f : botrightW[ch] * x55[Ww - 1];
                } else {
                    v = botz ? 0.0f : botW[ch] * (x54[c - 1] + x55[c - 1]);
                }
                op[(HO - 1) * WO + c] = v;
            }
        }

        // ---- interior rows r = 1..56: one warp per row, float2, batched loads ----
        const float wLr = leftz  ? 0.0f : leftW[ch];
        const float wRr = rightz ? 0.0f : rightW[ch];

        // Phase 1: issue all 7 loads (MLP = 7)
        float2 g[7];
        #pragma unroll
        for (int k = 0; k < 7; k++) {
            g[k] = make_float2(0.0f, 0.0f);
            if (ld) g[k] = *(const float2*)(xp + (warp + 8 * k) * Ww + 2 * lane);
        }

        // Phase 2: shuffle + select + store
        #pragma unroll
        for (int k = 0; k < 7; k++) {
            const int r = 1 + warp + 8 * k;
            const float upx = __shfl_up_sync(0xffffffffu, g[k].x, 1);
            const float upy = __shfl_up_sync(0xffffffffu, g[k].y, 1);
            if (st) {
                const float o_lo = (lane == 0)  ? wLr * (g[k].x + g[k].y) : upy;
                const float o_hi = (lane == 28) ? wRr * (upx + upy)       : g[k].x;
                *(float2*)(op + r * WO + 2 * lane) = make_float2(o_lo, o_hi);
            }
        }
    }
}

extern "C" void kernel_launch(void* const* d_in, const int* in_sizes, int n_in,
                              void* d_out, int out_size)
{
    const float* x         = (const float*)d_in[0];
    const float* topW      = (const float*)d_in[1];
    const float* botW      = (const float*)d_in[2];
    const float* leftW     = (const float*)d_in[3];
    const float* rightW    = (const float*)d_in[4];
    const float* topleftW  = (const float*)d_in[5];
    const float* toprightW = (const float*)d_in[6];
    const float* botleftW  = (const float*)d_in[7];
    const float* botrightW = (const float*)d_in[8];
    const int*   num_patches = (const int*)d_in[10];

    const int planes = in_sizes[0] / PLANE_IN;   // b * C = 16384

    int grid = 148 * 8;
    if (grid > planes) grid = planes;

    weight_pad2d_kernel<<<grid, 256>>>(
        x, topW, botW, leftW, rightW,
        topleftW, toprightW, botleftW, botrightW,
        num_patches, planes, (float*)d_out);
}

// round 13
// speedup vs baseline: 1.1417x; 1.0340x over previous
#include <cuda_runtime.h>
#include <cstdint>

#define Hh 56
#define Ww 56
#define HO 58
#define WO 58
#define PLANE_IN  3136           // 56*56
#define PLANE_OUT 3364           // 58*58
#define PLANE_BYTES (PLANE_IN * 4)   // 12544, multiple of 16
// C fixed at 128 by the generator
#define C_LOG2 7
#define C_MASK 127

__device__ __forceinline__ uint32_t smem_u32(const void* p) {
    uint32_t a;
    asm("{ .reg .u64 t; cvta.to.shared.u64 t, %1; cvt.u32.u64 %0, t; }"
        : "=r"(a) : "l"(p));
    return a;
}

__device__ __forceinline__ void mbar_wait(uint32_t mbar, int phase) {
    asm volatile(
        "{\n\t"
        ".reg .pred P;\n\t"
        "WAIT_%=:\n\t"
        "mbarrier.try_wait.parity.acquire.cta.shared::cta.b64 P, [%0], %1, 0x989680;\n\t"
        "@P bra.uni DONE_%=;\n\t"
        "bra.uni WAIT_%=;\n\t"
        "DONE_%=:\n\t"
        "}"
        :: "r"(mbar), "r"(phase) : "memory");
}

__device__ __forceinline__ void tma_issue(uint32_t dst, const float* src, uint32_t mbar) {
    asm volatile(
        "mbarrier.arrive.expect_tx.shared.b64 _, [%0], %1;"
        :: "r"(mbar), "r"((uint32_t)PLANE_BYTES) : "memory");
    asm volatile(
        "cp.async.bulk.shared::cta.global.mbarrier::complete_tx::bytes [%0], [%1], %2, [%3];"
        :: "r"(dst), "l"(src), "r"((uint32_t)PLANE_BYTES), "r"(mbar) : "memory");
}

struct __align__(16) Smem {
    float buf[2][PLANE_IN];
    unsigned long long mbar[2];
};

__global__ void __launch_bounds__(256, 8)
weight_pad2d_kernel(const float* __restrict__ x,
                    const float* __restrict__ topW,
                    const float* __restrict__ botW,
                    const float* __restrict__ leftW,
                    const float* __restrict__ rightW,
                    const float* __restrict__ topleftW,
                    const float* __restrict__ toprightW,
                    const float* __restrict__ botleftW,
                    const float* __restrict__ botrightW,
                    const int* __restrict__ num_patches_ptr,
                    int planes,
                    float* __restrict__ out)
{
    __shared__ Smem sm;

    const int tid  = threadIdx.x;
    const int warp = tid >> 5;           // 0..7
    const int lane = tid & 31;

    const int P  = *num_patches_ptr;
    const int PP = P * P;

    const uint32_t mb[2] = { smem_u32(&sm.mbar[0]), smem_u32(&sm.mbar[1]) };
    const uint32_t bufaddr[2] = { smem_u32(&sm.buf[0][0]), smem_u32(&sm.buf[1][0]) };

    if (tid == 0) {
        asm volatile("mbarrier.init.shared.b64 [%0], 1;" :: "r"(mb[0]) : "memory");
        asm volatile("mbarrier.init.shared.b64 [%0], 1;" :: "r"(mb[1]) : "memory");
        asm volatile("fence.proxy.async.shared::cta;" ::: "memory");
    }
    __syncthreads();

    int plane = blockIdx.x;
    // prologue: fetch first plane into buf[0]
    if (tid == 0 && plane < planes) {
        tma_issue(bufaddr[0], x + (size_t)plane * PLANE_IN, mb[0]);
    }

    int ph0 = 0, ph1 = 0;
    int it = 0;
    for (; plane < planes; plane += gridDim.x, ++it) {
        const int cur = it & 1;
        const int nplane = plane + gridDim.x;

        // issue next plane's bulk copy into the other buffer (consumed last iter,
        // reads fenced by the trailing __syncthreads of the previous iteration)
        if (tid == 0 && nplane < planes) {
            tma_issue(bufaddr[cur ^ 1], x + (size_t)nplane * PLANE_IN, mb[cur ^ 1]);
        }

        // masks / weights — overlaps the TMA
        const int bidx = plane >> C_LOG2;
        const int ch   = plane & C_MASK;
        const unsigned q1 = (unsigned)bidx / (unsigned)P;
        const int colp    = bidx - (int)(q1 * (unsigned)P);       // bidx % P
        const unsigned q2 = (unsigned)bidx / (unsigned)PP;
        const int within  = bidx - (int)(q2 * (unsigned)PP);      // bidx % PP
        const bool topz   = within < P;
        const bool botz   = within >= PP - P;
        const bool leftz  = colp == 0;
        const bool rightz = colp == (P - 1);

        const float wLr = leftz  ? 0.0f : leftW[ch];
        const float wRr = rightz ? 0.0f : rightW[ch];

        // wait for current buffer
        if (cur == 0) { mbar_wait(mb[0], ph0); ph0 ^= 1; }
        else          { mbar_wait(mb[1], ph1); ph1 ^= 1; }

        const float* __restrict__ S = sm.buf[cur];
        float*       __restrict__ op = out + (size_t)plane * PLANE_OUT;

        // ---- interior rows r = 1..56: one warp per row, from SMEM, no shuffles ----
        // lane 0:  (wL*(s0+s1), s0)
        // lane l (1..27): (s[2l-1], s[2l])
        // lane 28: (s55, wR*(s54+s55))
        if (lane < 29) {
            const int p = (lane == 0) ? 0 : ((lane == 28) ? 54 : 2 * lane - 1);
            #pragma unroll
            for (int k = 0; k < 7; k++) {
                const int r = 1 + warp + 8 * k;
                const float* s = S + (r - 1) * Ww;
                const float a = s[p];
                const float b = s[p + 1];
                const float lo = (lane == 0)  ? wLr * (a + b) : ((lane == 28) ? b : a);
                const float hi = (lane == 28) ? wRr * (a + b) : ((lane == 0) ? a : b);
                *(float2*)(op + r * WO + 2 * lane) = make_float2(lo, hi);
            }
        }

        // ---- top row r=0 (warps 0,1, scalar from SMEM rows 0,1) ----
        if (tid < 64) {
            const int c = tid;
            if (c < WO) {
                float v;
                if (c == 0) {
                    v = (topz || leftz) ? 0.0f : topleftW[ch] * S[0];
                } else if (c == WO - 1) {
                    v = (topz || rightz) ? 0.0f : toprightW[ch] * S[Ww - 1];
                } else {
                    v = topz ? 0.0f : topW[ch] * (S[c - 1] + S[Ww + c - 1]);
                }
                op[c] = v;
            }
        } else if (tid < 128) {
            // ---- bottom row r=57 (warps 2,3, scalar from SMEM rows 54,55) ----
            const int c = tid - 64;
            if (c < WO) {
                const float* s54 = S + (Hh - 2) * Ww;
                const float* s55 = S + (Hh - 1) * Ww;
                float v;
                if (c == 0) {
                    v = (botz || leftz) ? 0.0f : botleftW[ch] * s55[0];
                } else if (c == WO - 1) {
                    v = (botz || rightz) ? 0.0f : botrightW[ch] * s55[Ww - 1];
                } else {
                    v = botz ? 0.0f : botW[ch] * (s54[c - 1] + s55[c - 1]);
                }
                op[(HO - 1) * WO + c] = v;
            }
        }

        // all reads of buf[cur] done before it is refilled next iteration
        __syncthreads();
    }
}

extern "C" void kernel_launch(void* const* d_in, const int* in_sizes, int n_in,
                              void* d_out, int out_size)
{
    const float* x         = (const float*)d_in[0];
    const float* topW      = (const float*)d_in[1];
    const float* botW      = (const float*)d_in[2];
    const float* leftW     = (const float*)d_in[3];
    const float* rightW    = (const float*)d_in[4];
    const float* topleftW  = (const float*)d_in[5];
    const float* toprightW = (const float*)d_in[6];
    const float* botleftW  = (const float*)d_in[7];
    const float* botrightW = (const float*)d_in[8];
    const int*   num_patches = (const int*)d_in[10];

    const int planes = in_sizes[0] / PLANE_IN;   // b * C = 16384

    int grid = 148 * 8;
    if (grid > planes) grid = planes;

    weight_pad2d_kernel<<<grid, 256>>>(
        x, topW, botW, leftW, rightW,
        topleftW, toprightW, botleftW, botrightW,
        num_patches, planes, (float*)d_out);
}

// round 14
// speedup vs baseline: 1.1655x; 1.0208x over previous
#include <cuda_runtime.h>
#include <cstdint>

#define Hh 56
#define Ww 56
#define HO 58
#define WO 58
#define PLANE_IN  3136           // 56*56
#define PLANE_OUT 3364           // 58*58
#define PLANE_BYTES (PLANE_IN * 4)   // 12544, multiple of 16
// C fixed at 128 by the generator
#define C_LOG2 7
#define C_MASK 127

__device__ __forceinline__ uint32_t smem_u32(const void* p) {
    uint32_t a;
    asm("{ .reg .u64 t; cvta.to.shared.u64 t, %1; cvt.u32.u64 %0, t; }"
        : "=r"(a) : "l"(p));
    return a;
}

__device__ __forceinline__ void mbar_wait(uint32_t mbar, int phase) {
    asm volatile(
        "{\n\t"
        ".reg .pred P;\n\t"
        "WAIT_%=:\n\t"
        "mbarrier.try_wait.parity.acquire.cta.shared::cta.b64 P, [%0], %1, 0x989680;\n\t"
        "@P bra.uni DONE_%=;\n\t"
        "bra.uni WAIT_%=;\n\t"
        "DONE_%=:\n\t"
        "}"
        :: "r"(mbar), "r"(phase) : "memory");
}

__device__ __forceinline__ void tma_issue(uint32_t dst, const float* src, uint32_t mbar) {
    asm volatile(
        "mbarrier.arrive.expect_tx.shared.b64 _, [%0], %1;"
        :: "r"(mbar), "r"((uint32_t)PLANE_BYTES) : "memory");
    asm volatile(
        "cp.async.bulk.shared::cta.global.mbarrier::complete_tx::bytes [%0], [%1], %2, [%3];"
        :: "r"(dst), "l"(src), "r"((uint32_t)PLANE_BYTES), "r"(mbar) : "memory");
}

struct __align__(16) Smem {
    float buf[2][PLANE_IN];
    unsigned long long mbar[2];
};

__global__ void __launch_bounds__(256, 8)
weight_pad2d_kernel(const float* __restrict__ x,
                    const float* __restrict__ topW,
                    const float* __restrict__ botW,
                    const float* __restrict__ leftW,
                    const float* __restrict__ rightW,
                    const float* __restrict__ topleftW,
                    const float* __restrict__ toprightW,
                    const float* __restrict__ botleftW,
                    const float* __restrict__ botrightW,
                    const int* __restrict__ num_patches_ptr,
                    int planes,
                    float* __restrict__ out)
{
    __shared__ Smem sm;

    const int tid  = threadIdx.x;
    const int warp = tid >> 5;           // 0..7
    const int lane = tid & 31;

    const int P  = *num_patches_ptr;
    const int PP = P * P;

    const uint32_t mb[2] = { smem_u32(&sm.mbar[0]), smem_u32(&sm.mbar[1]) };
    const uint32_t bufaddr[2] = { smem_u32(&sm.buf[0][0]), smem_u32(&sm.buf[1][0]) };

    if (tid == 0) {
        asm volatile("mbarrier.init.shared.b64 [%0], 1;" :: "r"(mb[0]) : "memory");
        asm volatile("mbarrier.init.shared.b64 [%0], 1;" :: "r"(mb[1]) : "memory");
        asm volatile("fence.proxy.async.shared::cta;" ::: "memory");
    }
    __syncthreads();

    const bool ld = (lane < 28);   // lanes 0..27 read SMEM
    const bool st = (lane < 29);   // lanes 0..28 store

    int plane = blockIdx.x;
    // prologue: fetch first plane into buf[0]
    if (tid == 0 && plane < planes) {
        tma_issue(bufaddr[0], x + (size_t)plane * PLANE_IN, mb[0]);
    }

    int ph0 = 0, ph1 = 0;
    int it = 0;
    for (; plane < planes; plane += gridDim.x, ++it) {
        const int cur = it & 1;
        const int nplane = plane + gridDim.x;

        // issue next plane's bulk copy into the other buffer (consumed last iter,
        // reads fenced by the trailing __syncthreads of the previous iteration)
        if (tid == 0 && nplane < planes) {
            tma_issue(bufaddr[cur ^ 1], x + (size_t)nplane * PLANE_IN, mb[cur ^ 1]);
        }

        // masks / weights — overlaps the TMA
        const int bidx = plane >> C_LOG2;
        const int ch   = plane & C_MASK;
        const unsigned q1 = (unsigned)bidx / (unsigned)P;
        const int colp    = bidx - (int)(q1 * (unsigned)P);       // bidx % P
        const unsigned q2 = (unsigned)bidx / (unsigned)PP;
        const int within  = bidx - (int)(q2 * (unsigned)PP);      // bidx % PP
        const bool topz   = within < P;
        const bool botz   = within >= PP - P;
        const bool leftz  = colp == 0;
        const bool rightz = colp == (P - 1);

        const float wLr = leftz  ? 0.0f : leftW[ch];
        const float wRr = rightz ? 0.0f : rightW[ch];

        // wait for current buffer
        if (cur == 0) { mbar_wait(mb[0], ph0); ph0 ^= 1; }
        else          { mbar_wait(mb[1], ph1); ph1 ^= 1; }

        const float* __restrict__ S = sm.buf[cur];
        float*       __restrict__ op = out + (size_t)plane * PLANE_OUT;

        // ---- interior rows r = 1..56: one warp per row; aligned LDS.64 (no
        //      bank conflicts) + 2 shuffles; exact R11 mapping ----
        #pragma unroll
        for (int k = 0; k < 7; k++) {
            const int r = 1 + warp + 8 * k;
            float2 g = make_float2(0.0f, 0.0f);
            if (ld) g = *(const float2*)(S + (r - 1) * Ww + 2 * lane);
            const float upx = __shfl_up_sync(0xffffffffu, g.x, 1);
            const float upy = __shfl_up_sync(0xffffffffu, g.y, 1);
            if (st) {
                const float o_lo = (lane == 0)  ? wLr * (g.x + g.y) : upy;
                const float o_hi = (lane == 28) ? wRr * (upx + upy) : g.x;
                *(float2*)(op + r * WO + 2 * lane) = make_float2(o_lo, o_hi);
            }
        }

        // ---- top row r=0 (warp 0; SMEM rows 0,1; R7 edge mapping) ----
        if (warp == 0) {
            float2 g0 = make_float2(0.0f, 0.0f), g1 = make_float2(0.0f, 0.0f);
            if (ld) {
                g0 = *(const float2*)(S + 2 * lane);
                g1 = *(const float2*)(S + Ww + 2 * lane);
            }
            const float wT = topz ? 0.0f : topW[ch];
            const float tl = (topz || leftz)  ? 0.0f : topleftW[ch];
            const float tr = (topz || rightz) ? 0.0f : toprightW[ch];
            const float2 h = make_float2(g0.x + g1.x, g0.y + g1.y);
            const float hup   = __shfl_up_sync(0xffffffffu, h.y, 1);
            const float g0yup = __shfl_up_sync(0xffffffffu, g0.y, 1);
            if (st) {
                const float o_lo = (lane == 0)  ? tl * g0.x : wT * hup;
                const float o_hi = (lane == 28) ? tr * g0yup : wT * h.x;
                *(float2*)(op + 2 * lane) = make_float2(o_lo, o_hi);
            }
        }

        // ---- bottom row r=57 (warp 7; SMEM rows 55(gb), 54(ga)) ----
        if (warp == 7) {
            float2 gb = make_float2(0.0f, 0.0f), ga = make_float2(0.0f, 0.0f);
            if (ld) {
                gb = *(const float2*)(S + (Hh - 1) * Ww + 2 * lane);
                ga = *(const float2*)(S + (Hh - 2) * Ww + 2 * lane);
            }
            const float wB = botz ? 0.0f : botW[ch];
            const float bl = (botz || leftz)  ? 0.0f : botleftW[ch];
            const float br = (botz || rightz) ? 0.0f : botrightW[ch];
            const float2 h = make_float2(gb.x + ga.x, gb.y + ga.y);
            const float hup   = __shfl_up_sync(0xffffffffu, h.y, 1);
            const float gbyup = __shfl_up_sync(0xffffffffu, gb.y, 1);
            if (st) {
                const float o_lo = (lane == 0)  ? bl * gb.x : wB * hup;
                const float o_hi = (lane == 28) ? br * gbyup : wB * h.x;
                *(float2*)(op + (HO - 1) * WO + 2 * lane) = make_float2(o_lo, o_hi);
            }
        }

        // all reads of buf[cur] done before it is refilled next iteration
        __syncthreads();
    }
}

extern "C" void kernel_launch(void* const* d_in, const int* in_sizes, int n_in,
                              void* d_out, int out_size)
{
    const float* x         = (const float*)d_in[0];
    const float* topW      = (const float*)d_in[1];
    const float* botW      = (const float*)d_in[2];
    const float* leftW     = (const float*)d_in[3];
    const float* rightW    = (const float*)d_in[4];
    const float* topleftW  = (const float*)d_in[5];
    const float* toprightW = (const float*)d_in[6];
    const float* botleftW  = (const float*)d_in[7];
    const float* botrightW = (const float*)d_in[8];
    const int*   num_patches = (const int*)d_in[10];

    const int planes = in_sizes[0] / PLANE_IN;   // b * C = 16384

    int grid = 148 * 8;
    if (grid > planes) grid = planes;

    weight_pad2d_kernel<<<grid, 256>>>(
        x, topW, botW, leftW, rightW,
        topleftW, toprightW, botleftW, botrightW,
        num_patches, planes, (float*)d_out);
}